// round 14
// baseline (speedup 1.0000x reference)
#include <cuda_runtime.h>
#include <cuda_bf16.h>
#include <math.h>
#include <stdint.h>

#define BATCH   4
#define SEQLEN  4096
#define DMODEL  1024
#define DINNER  2048
#define DSTATE  16
#define NTOK    (BATCH*SEQLEN)      /* 16384 */
#define CHUNK   256
#define NCH     (SEQLEN/CHUNK)      /* 16 */
#define LOG2E   1.4426950408889634f

#define NW_ROWS (2*DINNER + 128)
#define NFUSED  (2*DINNER + 128)    /* 4224 */

/* ---------------- scratch (device globals; no allocation allowed) ---------------- */
__device__ float g_xinner[NTOK*DINNER];
__device__ float g_xc    [NTOK*DINNER];
__device__ float g_delta [NTOK*DINNER];
__device__ float g_Bm    [NTOK*DSTATE];
__device__ float g_Cm    [NTOK*DSTATE];
__device__ float g_ap    [BATCH*DINNER*NCH*DSTATE];
__device__ float g_he    [BATCH*DINNER*NCH*DSTATE];
__device__ __nv_bfloat16 g_xhi[NTOK*DMODEL];
__device__ __nv_bfloat16 g_xlo[NTOK*DMODEL];
__device__ __nv_bfloat16 g_whi[NW_ROWS*DMODEL];
__device__ __nv_bfloat16 g_wlo[NW_ROWS*DMODEL];
__device__ __nv_bfloat16 g_w2hi[DMODEL*DINNER];
__device__ __nv_bfloat16 g_w2lo[DMODEL*DINNER];
__device__ __nv_bfloat16 g_yhi[NTOK*DINNER];
__device__ __nv_bfloat16 g_ylo[NTOK*DINNER];

/* ============================ PTX helpers ======================================== */
__device__ __forceinline__ uint32_t smem_u32(const void* p){
    uint32_t a;
    asm("{ .reg .u64 t; cvta.to.shared.u64 t, %1; cvt.u32.u64 %0, t; }" : "=r"(a) : "l"(p));
    return a;
}
__device__ __forceinline__ float ex2f(float x){
    float y; asm("ex2.approx.f32 %0, %1;" : "=f"(y) : "f"(x)); return y;
}
__device__ __forceinline__ void cpa16(uint32_t dst, const void* src){
    asm volatile("cp.async.cg.shared.global [%0], [%1], 16;" :: "r"(dst), "l"(src));
}
__device__ __forceinline__ void ldsm4(uint32_t& r0, uint32_t& r1, uint32_t& r2, uint32_t& r3,
                                      uint32_t addr){
    asm volatile("ldmatrix.sync.aligned.m8n8.x4.shared.b16 {%0,%1,%2,%3}, [%4];"
                 : "=r"(r0), "=r"(r1), "=r"(r2), "=r"(r3) : "r"(addr));
}
__device__ __forceinline__ void mma16816(float* c, const uint32_t* a, const uint32_t* b){
    asm volatile(
        "mma.sync.aligned.m16n8k16.row.col.f32.bf16.bf16.f32 "
        "{%0,%1,%2,%3}, {%4,%5,%6,%7}, {%8,%9}, {%0,%1,%2,%3};"
        : "+f"(c[0]), "+f"(c[1]), "+f"(c[2]), "+f"(c[3])
        : "r"(a[0]), "r"(a[1]), "r"(a[2]), "r"(a[3]), "r"(b[0]), "r"(b[1]));
}

/* ====================== fp32 -> (bf16 hi, bf16 lo) split ========================= */
__device__ __forceinline__ void split4(const float* __restrict__ src,
                                       __nv_bfloat16* __restrict__ hi,
                                       __nv_bfloat16* __restrict__ lo, int i)
{
    float4 v = reinterpret_cast<const float4*>(src)[i];
    __nv_bfloat16 h0 = __float2bfloat16(v.x);
    __nv_bfloat16 h1 = __float2bfloat16(v.y);
    __nv_bfloat16 h2 = __float2bfloat16(v.z);
    __nv_bfloat16 h3 = __float2bfloat16(v.w);
    __nv_bfloat16 l0 = __float2bfloat16(v.x - __bfloat162float(h0));
    __nv_bfloat16 l1 = __float2bfloat16(v.y - __bfloat162float(h1));
    __nv_bfloat16 l2 = __float2bfloat16(v.z - __bfloat162float(h2));
    __nv_bfloat16 l3 = __float2bfloat16(v.w - __bfloat162float(h3));
    __nv_bfloat162* hp = reinterpret_cast<__nv_bfloat162*>(hi);
    __nv_bfloat162* lp = reinterpret_cast<__nv_bfloat162*>(lo);
    hp[2*i]   = __halves2bfloat162(h0, h1);
    hp[2*i+1] = __halves2bfloat162(h2, h3);
    lp[2*i]   = __halves2bfloat162(l0, l1);
    lp[2*i+1] = __halves2bfloat162(l2, l3);
}

__global__ __launch_bounds__(256)
void split_bf16(const float* __restrict__ src,
                __nv_bfloat16* __restrict__ hi,
                __nv_bfloat16* __restrict__ lo, int n4)
{
    int i = blockIdx.x * 256 + threadIdx.x;
    if (i < n4) split4(src, hi, lo, i);
}

#define XN4  (NTOK*DMODEL/4)
#define WN4  (DINNER*DMODEL/4)
#define BN4  (DSTATE*DMODEL/4)
#define ZN4  (96*DMODEL/4)
#define PRE_TOT (XN4 + 2*WN4 + 2*BN4 + ZN4)
__global__ __launch_bounds__(256)
void split_pre(const float* __restrict__ x,
               const float* __restrict__ w1,
               const float* __restrict__ w2,
               const float* __restrict__ bw,
               const float* __restrict__ cw,
               __nv_bfloat16* __restrict__ xhi, __nv_bfloat16* __restrict__ xlo,
               __nv_bfloat16* __restrict__ whi, __nv_bfloat16* __restrict__ wlo)
{
    int i = blockIdx.x * 256 + threadIdx.x;
    if (i < XN4) {
        split4(x, xhi, xlo, i);
    } else if (i < XN4 + WN4) {
        split4(w1, whi, wlo, i - XN4);
    } else if (i < XN4 + 2*WN4) {
        split4(w2, whi + (size_t)DINNER*DMODEL, wlo + (size_t)DINNER*DMODEL,
               i - XN4 - WN4);
    } else if (i < XN4 + 2*WN4 + BN4) {
        split4(bw, whi + (size_t)2*DINNER*DMODEL, wlo + (size_t)2*DINNER*DMODEL,
               i - XN4 - 2*WN4);
    } else if (i < XN4 + 2*WN4 + 2*BN4) {
        split4(cw, whi + ((size_t)2*DINNER + DSTATE)*DMODEL,
                   wlo + ((size_t)2*DINNER + DSTATE)*DMODEL,
               i - XN4 - 2*WN4 - BN4);
    } else if (i < PRE_TOT) {
        int j = i - XN4 - 2*WN4 - 2*BN4;
        __nv_bfloat162 z = __halves2bfloat162(__float2bfloat16(0.f), __float2bfloat16(0.f));
        __nv_bfloat162* hp = reinterpret_cast<__nv_bfloat162*>(
            whi + ((size_t)2*DINNER + 32)*DMODEL);
        __nv_bfloat162* lp = reinterpret_cast<__nv_bfloat162*>(
            wlo + ((size_t)2*DINNER + 32)*DMODEL);
        hp[2*j] = z; hp[2*j+1] = z;
        lp[2*j] = z; lp[2*j+1] = z;
    }
}

/* ============ HMMA bf16x3 GEMM: C[M,N] = A[M,K] @ W[N,K]^T (fp32 out) ============ */
#define ROWB      80
#define A_TILE    (128*ROWB)
#define B_TILE    (128*ROWB)
#define STAGE_B   (2*A_TILE + 2*B_TILE)   /* 40960 */
#define SMEM_GEMM (2*STAGE_B)             /* 81920 */

__device__ __forceinline__ void load_stage(
    uint32_t stage, int tid, int m0, int n0, int k0, int K,
    const __nv_bfloat16* __restrict__ Ah, const __nv_bfloat16* __restrict__ Al,
    const __nv_bfloat16* __restrict__ Wh, const __nv_bfloat16* __restrict__ Wl)
{
    #pragma unroll
    for (int j = 0; j < 4; ++j) {
        const int idx  = tid + 256 * j;
        const int half = idx >> 9;
        const int rem  = idx & 511;
        const int row  = rem >> 2;
        const int c    = rem & 3;
        const __nv_bfloat16* gp = (half ? Al : Ah) + (size_t)(m0 + row) * K + k0 + c*8;
        cpa16(stage + half * A_TILE + row * ROWB + c * 16, gp);
    }
    #pragma unroll
    for (int j = 0; j < 4; ++j) {
        const int idx  = tid + 256 * j;
        const int half = idx >> 9;
        const int rem  = idx & 511;
        const int row  = rem >> 2;
        const int c    = rem & 3;
        const __nv_bfloat16* gp = (half ? Wl : Wh) + (size_t)(n0 + row) * K + k0 + c*8;
        cpa16(stage + 2 * A_TILE + half * B_TILE + row * ROWB + c * 16, gp);
    }
    asm volatile("cp.async.commit_group;" ::: "memory");
}

template<int EPI>
__global__ void __launch_bounds__(256, 2)
hmma_gemm(int M, int N, int K,
          const __nv_bfloat16* __restrict__ Ah, const __nv_bfloat16* __restrict__ Al,
          const __nv_bfloat16* __restrict__ Wh, const __nv_bfloat16* __restrict__ Wl,
          float* __restrict__ C0, float* __restrict__ C1,
          float* __restrict__ Bm, float* __restrict__ Cm,
          const float* __restrict__ dtb)
{
    extern __shared__ char smem[];
    const uint32_t sb = smem_u32(smem);
    const int tid  = threadIdx.x;
    const int wid  = tid >> 5;
    const int lane = tid & 31;
    const int wy   = wid & 1;
    const int wx   = wid >> 1;
    const int m0 = blockIdx.y * 128, n0 = blockIdx.x * 128;

    float acc[4][4][4];
    #pragma unroll
    for (int i = 0; i < 4; ++i)
        #pragma unroll
        for (int j = 0; j < 4; ++j)
            #pragma unroll
            for (int e = 0; e < 4; ++e) acc[i][j][e] = 0.f;

    const int KT = K >> 5;

    load_stage(sb + 0*STAGE_B, tid, m0, n0,  0, K, Ah, Al, Wh, Wl);
    if (KT > 1) load_stage(sb + 1*STAGE_B, tid, m0, n0, 32, K, Ah, Al, Wh, Wl);

    const int arow = lane & 15;
    const int acol = (lane >> 4) * 16;
    const int brow = (lane & 7) + ((lane >> 4) << 3);
    const int bcol = ((lane >> 3) & 1) * 16;

    for (int kt = 0; kt < KT; ++kt) {
        if (kt + 1 < KT) asm volatile("cp.async.wait_group 1;" ::: "memory");
        else             asm volatile("cp.async.wait_group 0;" ::: "memory");
        __syncthreads();

        const uint32_t st  = sb + (kt & 1) * STAGE_B;
        const uint32_t stb = st + 2 * A_TILE;
        #pragma unroll
        for (int ks = 0; ks < 2; ++ks) {
            uint32_t ah[4][4], al[4][4], bh[4][2], bl[4][2];
            #pragma unroll
            for (int mi = 0; mi < 4; ++mi) {
                uint32_t ra = st + (uint32_t)((wy*64 + mi*16 + arow) * ROWB + ks*32 + acol);
                ldsm4(ah[mi][0], ah[mi][1], ah[mi][2], ah[mi][3], ra);
                ldsm4(al[mi][0], al[mi][1], al[mi][2], al[mi][3], ra + A_TILE);
            }
            #pragma unroll
            for (int p = 0; p < 2; ++p) {
                uint32_t rb = stb + (uint32_t)((wx*32 + p*16 + brow) * ROWB + ks*32 + bcol);
                ldsm4(bh[2*p][0], bh[2*p][1], bh[2*p+1][0], bh[2*p+1][1], rb);
                ldsm4(bl[2*p][0], bl[2*p][1], bl[2*p+1][0], bl[2*p+1][1], rb + B_TILE);
            }
            #pragma unroll
            for (int mi = 0; mi < 4; ++mi)
                #pragma unroll
                for (int ni = 0; ni < 4; ++ni) {
                    mma16816(acc[mi][ni], ah[mi], bh[ni]);
                    mma16816(acc[mi][ni], ah[mi], bl[ni]);
                    mma16816(acc[mi][ni], al[mi], bh[ni]);
                }
        }
        __syncthreads();
        if (kt + 2 < KT)
            load_stage(st, tid, m0, n0, (kt + 2) * 32, K, Ah, Al, Wh, Wl);
    }

    const int r0 = lane >> 2;
    const int c0 = (lane & 3) * 2;
    #pragma unroll
    for (int mi = 0; mi < 4; ++mi)
        #pragma unroll
        for (int ni = 0; ni < 4; ++ni) {
            const int row = m0 + wy*64 + mi*16 + r0;
            const int col = n0 + wx*32 + ni*8 + c0;
            if (EPI == 0) {
                *reinterpret_cast<float2*>(C0 + (size_t)row * N + col) =
                    make_float2(acc[mi][ni][0], acc[mi][ni][1]);
                *reinterpret_cast<float2*>(C0 + (size_t)(row + 8) * N + col) =
                    make_float2(acc[mi][ni][2], acc[mi][ni][3]);
            } else {
                if (col < DINNER) {
                    *reinterpret_cast<float2*>(C0 + (size_t)row * DINNER + col) =
                        make_float2(acc[mi][ni][0], acc[mi][ni][1]);
                    *reinterpret_cast<float2*>(C0 + (size_t)(row + 8) * DINNER + col) =
                        make_float2(acc[mi][ni][2], acc[mi][ni][3]);
                } else if (col < 2*DINNER) {
                    const int dc = col - DINNER;
                    const float b0 = dtb[dc], b1 = dtb[dc + 1];
                    float z0 = acc[mi][ni][0] + b0, z1 = acc[mi][ni][1] + b1;
                    float z2 = acc[mi][ni][2] + b0, z3 = acc[mi][ni][3] + b1;
                    z0 = (z0 > 20.f) ? z0 : log1pf(__expf(z0));
                    z1 = (z1 > 20.f) ? z1 : log1pf(__expf(z1));
                    z2 = (z2 > 20.f) ? z2 : log1pf(__expf(z2));
                    z3 = (z3 > 20.f) ? z3 : log1pf(__expf(z3));
                    *reinterpret_cast<float2*>(C1 + (size_t)row * DINNER + dc) =
                        make_float2(z0, z1);
                    *reinterpret_cast<float2*>(C1 + (size_t)(row + 8) * DINNER + dc) =
                        make_float2(z2, z3);
                } else if (col < 2*DINNER + DSTATE) {
                    const int nn = col - 2*DINNER;
                    *reinterpret_cast<float2*>(Bm + (size_t)row * DSTATE + nn) =
                        make_float2(acc[mi][ni][0], acc[mi][ni][1]);
                    *reinterpret_cast<float2*>(Bm + (size_t)(row + 8) * DSTATE + nn) =
                        make_float2(acc[mi][ni][2], acc[mi][ni][3]);
                } else if (col < 2*DINNER + 2*DSTATE) {
                    const int nn = col - 2*DINNER - DSTATE;
                    *reinterpret_cast<float2*>(Cm + (size_t)row * DSTATE + nn) =
                        make_float2(acc[mi][ni][0], acc[mi][ni][1]);
                    *reinterpret_cast<float2*>(Cm + (size_t)(row + 8) * DSTATE + nn) =
                        make_float2(acc[mi][ni][2], acc[mi][ni][3]);
                }
            }
        }
}

/* ------- depthwise causal conv1d + bias + SiLU -> xc (4 channels/thread) --------- */
#define CTS 64
__global__ void conv_silu(const float* __restrict__ xin,
                          const float* __restrict__ cw,
                          const float* __restrict__ cb,
                          float* __restrict__ xc)
{
    const int d4 = blockIdx.x * blockDim.x + threadIdx.x;
    const int d  = d4 * 4;
    const int b  = blockIdx.z;
    const int t0 = blockIdx.y * CTS;

    float w[4][4], bias[4];
    #pragma unroll
    for (int j = 0; j < 4; ++j) {
        w[j][0] = cw[(d+j)*4+0]; w[j][1] = cw[(d+j)*4+1];
        w[j][2] = cw[(d+j)*4+2]; w[j][3] = cw[(d+j)*4+3];
        bias[j] = cb[d+j];
    }

    const float4* base = reinterpret_cast<const float4*>(
        xin + (size_t)b * SEQLEN * DINNER) + d4;
    const float4 z4 = make_float4(0.f, 0.f, 0.f, 0.f);
    float4 xm3 = (t0 - 3 >= 0) ? base[(size_t)(t0-3) * (DINNER/4)] : z4;
    float4 xm2 = (t0 - 2 >= 0) ? base[(size_t)(t0-2) * (DINNER/4)] : z4;
    float4 xm1 = (t0 - 1 >= 0) ? base[(size_t)(t0-1) * (DINNER/4)] : z4;

    float4* out = reinterpret_cast<float4*>(xc + (size_t)b * SEQLEN * DINNER) + d4;

    #pragma unroll 4
    for (int t = t0; t < t0 + CTS; ++t) {
        float4 cur = base[(size_t)t * (DINNER/4)];
        const float m3[4] = {xm3.x, xm3.y, xm3.z, xm3.w};
        const float m2[4] = {xm2.x, xm2.y, xm2.z, xm2.w};
        const float m1[4] = {xm1.x, xm1.y, xm1.z, xm1.w};
        const float cu[4] = {cur.x, cur.y, cur.z, cur.w};
        float o[4];
        #pragma unroll
        for (int j = 0; j < 4; ++j) {
            float v = fmaf(w[j][0], m3[j], fmaf(w[j][1], m2[j],
                       fmaf(w[j][2], m1[j], fmaf(w[j][3], cu[j], bias[j]))));
            float sig = 1.f / (1.f + __expf(-v));
            o[j] = v * sig;
        }
        out[(size_t)t * (DINNER/4)] = make_float4(o[0], o[1], o[2], o[3]);
        xm3 = xm2; xm2 = xm1; xm1 = cur;
    }
}

/* ------- scan pass 1 (1 ch/thread): Σdt trick + ex2 + float4 Bs loads ------------ */
__global__ __launch_bounds__(128)
void scan_pass1(const float* __restrict__ delta, const float* __restrict__ xc,
                const float* __restrict__ Bm, const float* __restrict__ A_log,
                float* __restrict__ ap_out, float* __restrict__ he_out)
{
    __shared__ float Bs[CHUNK*DSTATE];
    const int tid = threadIdx.x;
    const int d = blockIdx.x * 128 + tid;
    const int c = blockIdx.y, b = blockIdx.z;

    const float* Bsrc = Bm + ((size_t)b * SEQLEN + (size_t)c * CHUNK) * DSTATE;
    for (int i = tid; i < CHUNK*DSTATE; i += 128) Bs[i] = Bsrc[i];
    __syncthreads();
    const float4* Bs4 = reinterpret_cast<const float4*>(Bs);

    float A2[DSTATE];
    #pragma unroll
    for (int s = 0; s < DSTATE; ++s)
        A2[s] = -expf(A_log[d*DSTATE + s]) * LOG2E;

    float h[DSTATE];
    #pragma unroll
    for (int s = 0; s < DSTATE; ++s) h[s] = 0.f;
    float sdt = 0.f;

    const size_t rowbase = ((size_t)b * SEQLEN + (size_t)c * CHUNK) * DINNER + d;
    const float* dptr = delta + rowbase;
    const float* xptr = xc + rowbase;

    for (int tl = 0; tl < CHUNK; ++tl) {
        float dt = dptr[(size_t)tl * DINNER];
        float xv = xptr[(size_t)tl * DINNER];
        float dx = dt * xv;
        sdt += dt;
        #pragma unroll
        for (int q = 0; q < 4; ++q) {
            float4 bq = Bs4[tl*4 + q];
            const float bv[4] = {bq.x, bq.y, bq.z, bq.w};
            #pragma unroll
            for (int e = 0; e < 4; ++e) {
                const int s = q*4 + e;
                float a = ex2f(dt * A2[s]);
                h[s] = fmaf(a, h[s], dx * bv[e]);
            }
        }
    }

    const size_t o = (((size_t)b * DINNER + d) * NCH + c) * DSTATE;
    #pragma unroll
    for (int s = 0; s < DSTATE; ++s) {
        ap_out[o+s] = ex2f(sdt * A2[s]);
        he_out[o+s] = h[s];
    }
}

/* ------- scan pass 2: sequential stitch over chunks; he buffer -> chunk inits ---- */
__global__ void scan_pass2(const float* __restrict__ ap, float* __restrict__ he)
{
    const int idx = blockIdx.x * blockDim.x + threadIdx.x;
    if (idx >= BATCH*DINNER) return;
    float h[DSTATE];
    #pragma unroll
    for (int s = 0; s < DSTATE; ++s) h[s] = 0.f;
    for (int c = 0; c < NCH; ++c) {
        const size_t o = ((size_t)idx * NCH + c) * DSTATE;
        #pragma unroll
        for (int s = 0; s < DSTATE; ++s) {
            float hin = h[s];
            h[s] = fmaf(ap[o+s], hin, he[o+s]);
            he[o+s] = hin;
        }
    }
}

/* --- scan pass 3 (1 ch/thread): ex2 + float4 Bs/Cs loads, emit bf16 hi/lo -------- */
__global__ __launch_bounds__(128)
void scan_pass3(const float* __restrict__ delta, const float* __restrict__ xc,
                const float* __restrict__ Bm, const float* __restrict__ Cm,
                const float* __restrict__ A_log, const float* __restrict__ Dv,
                const float* __restrict__ hinit,
                __nv_bfloat16* __restrict__ yhi, __nv_bfloat16* __restrict__ ylo)
{
    __shared__ float Bs[CHUNK*DSTATE];
    __shared__ float Cs[CHUNK*DSTATE];
    const int tid = threadIdx.x;
    const int d = blockIdx.x * 128 + tid;
    const int c = blockIdx.y, b = blockIdx.z;

    const float* Bsrc = Bm + ((size_t)b * SEQLEN + (size_t)c * CHUNK) * DSTATE;
    const float* Csrc = Cm + ((size_t)b * SEQLEN + (size_t)c * CHUNK) * DSTATE;
    for (int i = tid; i < CHUNK*DSTATE; i += 128) { Bs[i] = Bsrc[i]; Cs[i] = Csrc[i]; }
    __syncthreads();
    const float4* Bs4 = reinterpret_cast<const float4*>(Bs);
    const float4* Cs4 = reinterpret_cast<const float4*>(Cs);

    float A2[DSTATE];
    #pragma unroll
    for (int s = 0; s < DSTATE; ++s)
        A2[s] = -expf(A_log[d*DSTATE + s]) * LOG2E;

    float h[DSTATE];
    const size_t o0 = (((size_t)b * DINNER + d) * NCH + c) * DSTATE;
    #pragma unroll
    for (int s = 0; s < DSTATE; ++s) h[s] = hinit[o0+s];

    const float Dd = Dv[d];
    const size_t rowbase = ((size_t)b * SEQLEN + (size_t)c * CHUNK) * DINNER + d;
    const float* dptr = delta + rowbase;
    const float* xptr = xc + rowbase;
    __nv_bfloat16* yhp = yhi + rowbase;
    __nv_bfloat16* ylp = ylo + rowbase;

    for (int tl = 0; tl < CHUNK; ++tl) {
        float dt = dptr[(size_t)tl * DINNER];
        float xv = xptr[(size_t)tl * DINNER];
        float dx = dt * xv;
        float acc = 0.f;
        #pragma unroll
        for (int q = 0; q < 4; ++q) {
            float4 bq = Bs4[tl*4 + q];
            float4 cq = Cs4[tl*4 + q];
            const float bv[4] = {bq.x, bq.y, bq.z, bq.w};
            const float cv[4] = {cq.x, cq.y, cq.z, cq.w};
            #pragma unroll
            for (int e = 0; e < 4; ++e) {
                const int s = q*4 + e;
                float a = ex2f(dt * A2[s]);
                h[s] = fmaf(a, h[s], dx * bv[e]);
                acc = fmaf(h[s], cv[e], acc);
            }
        }
        float yv = fmaf(Dd, xv, acc);
        __nv_bfloat16 hb = __float2bfloat16(yv);
        __nv_bfloat16 lb = __float2bfloat16(yv - __bfloat162float(hb));
        yhp[(size_t)tl * DINNER] = hb;
        ylp[(size_t)tl * DINNER] = lb;
    }
}

/* -------------------------------- launcher --------------------------------------- */
extern "C" void kernel_launch(void* const* d_in, const int* in_sizes, int n_in,
                              void* d_out, int out_size)
{
    const float* x         = (const float*)d_in[0];
    const float* x_proj_w  = (const float*)d_in[1];
    const float* dt_proj_w = (const float*)d_in[2];
    const float* dt_proj_b = (const float*)d_in[3];
    const float* A_log     = (const float*)d_in[4];
    const float* Dvec      = (const float*)d_in[5];
    const float* B_proj_w  = (const float*)d_in[6];
    const float* C_proj_w  = (const float*)d_in[7];
    const float* conv_w    = (const float*)d_in[8];
    const float* conv_b    = (const float*)d_in[9];
    const float* out_proj_w= (const float*)d_in[10];
    float* out = (float*)d_out;

    float *xinner, *xc, *delta, *Bm, *Cm, *ap, *he;
    __nv_bfloat16 *xhi, *xlo, *whi, *wlo, *w2hi, *w2lo, *yhi, *ylo;
    cudaGetSymbolAddress((void**)&xinner, g_xinner);
    cudaGetSymbolAddress((void**)&xc,     g_xc);
    cudaGetSymbolAddress((void**)&delta,  g_delta);
    cudaGetSymbolAddress((void**)&Bm,     g_Bm);
    cudaGetSymbolAddress((void**)&Cm,     g_Cm);
    cudaGetSymbolAddress((void**)&ap,     g_ap);
    cudaGetSymbolAddress((void**)&he,     g_he);
    cudaGetSymbolAddress((void**)&xhi,    g_xhi);
    cudaGetSymbolAddress((void**)&xlo,    g_xlo);
    cudaGetSymbolAddress((void**)&whi,    g_whi);
    cudaGetSymbolAddress((void**)&wlo,    g_wlo);
    cudaGetSymbolAddress((void**)&w2hi,   g_w2hi);
    cudaGetSymbolAddress((void**)&w2lo,   g_w2lo);
    cudaGetSymbolAddress((void**)&yhi,    g_yhi);
    cudaGetSymbolAddress((void**)&ylo,    g_ylo);

    cudaFuncSetAttribute(hmma_gemm<0>, cudaFuncAttributeMaxDynamicSharedMemorySize, SMEM_GEMM);
    cudaFuncSetAttribute(hmma_gemm<1>, cudaFuncAttributeMaxDynamicSharedMemorySize, SMEM_GEMM);

    /* 1: split x + all GEMM1 weights */
    split_pre<<<PRE_TOT/256, 256>>>(x, x_proj_w, dt_proj_w, B_proj_w, C_proj_w,
                                    xhi, xlo, whi, wlo);

    /* 2: fused GEMM -> xinner, delta(softplus), Bm, Cm */
    hmma_gemm<1><<<dim3(NFUSED/128, NTOK/128), 256, SMEM_GEMM>>>(
        NTOK, NFUSED, DMODEL, xhi, xlo, whi, wlo, xinner, delta, Bm, Cm, dt_proj_b);

    /* 3: conv + SiLU -> xc */
    conv_silu<<<dim3(DINNER/4/256, SEQLEN/CTS, BATCH), 256>>>(xinner, conv_w, conv_b, xc);

    /* 4 (ncu target): scan pass 1, 1 channel/thread */
    scan_pass1<<<dim3(DINNER/128, NCH, BATCH), 128>>>(delta, xc, Bm, A_log, ap, he);

    scan_pass2<<<(BATCH*DINNER + 127)/128, 128>>>(ap, he);
    scan_pass3<<<dim3(DINNER/128, NCH, BATCH), 128>>>(delta, xc, Bm, Cm, A_log, Dvec,
                                                      he, yhi, ylo);

    split_bf16<<<DMODEL*DINNER/4/256, 256>>>(out_proj_w, w2hi, w2lo, DMODEL*DINNER/4);

    /* out = y @ out_proj_w^T */
    hmma_gemm<0><<<dim3(DMODEL/128, NTOK/128), 256, SMEM_GEMM>>>(
        NTOK, DMODEL, DINNER, yhi, ylo, w2hi, w2lo, out, nullptr, nullptr, nullptr, nullptr);
}

// round 15
// speedup vs baseline: 1.0411x; 1.0411x over previous
#include <cuda_runtime.h>
#include <cuda_bf16.h>
#include <math.h>
#include <stdint.h>

#define BATCH   4
#define SEQLEN  4096
#define DMODEL  1024
#define DINNER  2048
#define DSTATE  16
#define NTOK    (BATCH*SEQLEN)      /* 16384 */
#define CHUNK   256
#define NCH     (SEQLEN/CHUNK)      /* 16 */
#define LOG2E   1.4426950408889634f

#define NW_ROWS (2*DINNER + 128)
#define NFUSED  (2*DINNER + 128)    /* 4224 */

/* ---------------- scratch (device globals; no allocation allowed) ---------------- */
__device__ float g_xinner[NTOK*DINNER];
__device__ float g_xc    [NTOK*DINNER];
__device__ float g_delta [NTOK*DINNER];
__device__ float g_Bm    [NTOK*DSTATE];
__device__ float g_Cm    [NTOK*DSTATE];
__device__ float g_ap    [BATCH*DINNER*NCH*DSTATE];
__device__ float g_he    [BATCH*DINNER*NCH*DSTATE];
__device__ __nv_bfloat16 g_xhi[NTOK*DMODEL];
__device__ __nv_bfloat16 g_xlo[NTOK*DMODEL];
__device__ __nv_bfloat16 g_whi[NW_ROWS*DMODEL];
__device__ __nv_bfloat16 g_wlo[NW_ROWS*DMODEL];
__device__ __nv_bfloat16 g_w2hi[DMODEL*DINNER];
__device__ __nv_bfloat16 g_w2lo[DMODEL*DINNER];
__device__ __nv_bfloat16 g_yhi[NTOK*DINNER];
__device__ __nv_bfloat16 g_ylo[NTOK*DINNER];

/* ============================ PTX helpers ======================================== */
__device__ __forceinline__ uint32_t smem_u32(const void* p){
    uint32_t a;
    asm("{ .reg .u64 t; cvta.to.shared.u64 t, %1; cvt.u32.u64 %0, t; }" : "=r"(a) : "l"(p));
    return a;
}
__device__ __forceinline__ float ex2f(float x){
    float y; asm("ex2.approx.f32 %0, %1;" : "=f"(y) : "f"(x)); return y;
}
__device__ __forceinline__ void cpa16(uint32_t dst, const void* src){
    asm volatile("cp.async.cg.shared.global [%0], [%1], 16;" :: "r"(dst), "l"(src));
}
__device__ __forceinline__ void ldsm4(uint32_t& r0, uint32_t& r1, uint32_t& r2, uint32_t& r3,
                                      uint32_t addr){
    asm volatile("ldmatrix.sync.aligned.m8n8.x4.shared.b16 {%0,%1,%2,%3}, [%4];"
                 : "=r"(r0), "=r"(r1), "=r"(r2), "=r"(r3) : "r"(addr));
}
__device__ __forceinline__ void mma16816(float* c, const uint32_t* a, const uint32_t* b){
    asm volatile(
        "mma.sync.aligned.m16n8k16.row.col.f32.bf16.bf16.f32 "
        "{%0,%1,%2,%3}, {%4,%5,%6,%7}, {%8,%9}, {%0,%1,%2,%3};"
        : "+f"(c[0]), "+f"(c[1]), "+f"(c[2]), "+f"(c[3])
        : "r"(a[0]), "r"(a[1]), "r"(a[2]), "r"(a[3]), "r"(b[0]), "r"(b[1]));
}

/* ====================== fp32 -> (bf16 hi, bf16 lo) split ========================= */
__device__ __forceinline__ void split4(const float* __restrict__ src,
                                       __nv_bfloat16* __restrict__ hi,
                                       __nv_bfloat16* __restrict__ lo, int i)
{
    float4 v = reinterpret_cast<const float4*>(src)[i];
    __nv_bfloat16 h0 = __float2bfloat16(v.x);
    __nv_bfloat16 h1 = __float2bfloat16(v.y);
    __nv_bfloat16 h2 = __float2bfloat16(v.z);
    __nv_bfloat16 h3 = __float2bfloat16(v.w);
    __nv_bfloat16 l0 = __float2bfloat16(v.x - __bfloat162float(h0));
    __nv_bfloat16 l1 = __float2bfloat16(v.y - __bfloat162float(h1));
    __nv_bfloat16 l2 = __float2bfloat16(v.z - __bfloat162float(h2));
    __nv_bfloat16 l3 = __float2bfloat16(v.w - __bfloat162float(h3));
    __nv_bfloat162* hp = reinterpret_cast<__nv_bfloat162*>(hi);
    __nv_bfloat162* lp = reinterpret_cast<__nv_bfloat162*>(lo);
    hp[2*i]   = __halves2bfloat162(h0, h1);
    hp[2*i+1] = __halves2bfloat162(h2, h3);
    lp[2*i]   = __halves2bfloat162(l0, l1);
    lp[2*i+1] = __halves2bfloat162(l2, l3);
}

__global__ __launch_bounds__(256)
void split_bf16(const float* __restrict__ src,
                __nv_bfloat16* __restrict__ hi,
                __nv_bfloat16* __restrict__ lo, int n4)
{
    int i = blockIdx.x * 256 + threadIdx.x;
    if (i < n4) split4(src, hi, lo, i);
}

#define XN4  (NTOK*DMODEL/4)
#define WN4  (DINNER*DMODEL/4)
#define BN4  (DSTATE*DMODEL/4)
#define ZN4  (96*DMODEL/4)
#define PRE_TOT (XN4 + 2*WN4 + 2*BN4 + ZN4)
__global__ __launch_bounds__(256)
void split_pre(const float* __restrict__ x,
               const float* __restrict__ w1,
               const float* __restrict__ w2,
               const float* __restrict__ bw,
               const float* __restrict__ cw,
               __nv_bfloat16* __restrict__ xhi, __nv_bfloat16* __restrict__ xlo,
               __nv_bfloat16* __restrict__ whi, __nv_bfloat16* __restrict__ wlo)
{
    int i = blockIdx.x * 256 + threadIdx.x;
    if (i < XN4) {
        split4(x, xhi, xlo, i);
    } else if (i < XN4 + WN4) {
        split4(w1, whi, wlo, i - XN4);
    } else if (i < XN4 + 2*WN4) {
        split4(w2, whi + (size_t)DINNER*DMODEL, wlo + (size_t)DINNER*DMODEL,
               i - XN4 - WN4);
    } else if (i < XN4 + 2*WN4 + BN4) {
        split4(bw, whi + (size_t)2*DINNER*DMODEL, wlo + (size_t)2*DINNER*DMODEL,
               i - XN4 - 2*WN4);
    } else if (i < XN4 + 2*WN4 + 2*BN4) {
        split4(cw, whi + ((size_t)2*DINNER + DSTATE)*DMODEL,
                   wlo + ((size_t)2*DINNER + DSTATE)*DMODEL,
               i - XN4 - 2*WN4 - BN4);
    } else if (i < PRE_TOT) {
        int j = i - XN4 - 2*WN4 - 2*BN4;
        __nv_bfloat162 z = __halves2bfloat162(__float2bfloat16(0.f), __float2bfloat16(0.f));
        __nv_bfloat162* hp = reinterpret_cast<__nv_bfloat162*>(
            whi + ((size_t)2*DINNER + 32)*DMODEL);
        __nv_bfloat162* lp = reinterpret_cast<__nv_bfloat162*>(
            wlo + ((size_t)2*DINNER + 32)*DMODEL);
        hp[2*j] = z; hp[2*j+1] = z;
        lp[2*j] = z; lp[2*j+1] = z;
    }
}

/* ============ HMMA bf16x3 GEMM: C[M,N] = A[M,K] @ W[N,K]^T (fp32 out) ============ */
#define ROWB      80
#define A_TILE    (128*ROWB)
#define B_TILE    (128*ROWB)
#define STAGE_B   (2*A_TILE + 2*B_TILE)   /* 40960 */
#define SMEM_GEMM (2*STAGE_B)             /* 81920 */

__device__ __forceinline__ void load_stage(
    uint32_t stage, int tid, int m0, int n0, int k0, int K,
    const __nv_bfloat16* __restrict__ Ah, const __nv_bfloat16* __restrict__ Al,
    const __nv_bfloat16* __restrict__ Wh, const __nv_bfloat16* __restrict__ Wl)
{
    #pragma unroll
    for (int j = 0; j < 4; ++j) {
        const int idx  = tid + 256 * j;
        const int half = idx >> 9;
        const int rem  = idx & 511;
        const int row  = rem >> 2;
        const int c    = rem & 3;
        const __nv_bfloat16* gp = (half ? Al : Ah) + (size_t)(m0 + row) * K + k0 + c*8;
        cpa16(stage + half * A_TILE + row * ROWB + c * 16, gp);
    }
    #pragma unroll
    for (int j = 0; j < 4; ++j) {
        const int idx  = tid + 256 * j;
        const int half = idx >> 9;
        const int rem  = idx & 511;
        const int row  = rem >> 2;
        const int c    = rem & 3;
        const __nv_bfloat16* gp = (half ? Wl : Wh) + (size_t)(n0 + row) * K + k0 + c*8;
        cpa16(stage + 2 * A_TILE + half * B_TILE + row * ROWB + c * 16, gp);
    }
    asm volatile("cp.async.commit_group;" ::: "memory");
}

template<int EPI>
__global__ void __launch_bounds__(256, 2)
hmma_gemm(int M, int N, int K,
          const __nv_bfloat16* __restrict__ Ah, const __nv_bfloat16* __restrict__ Al,
          const __nv_bfloat16* __restrict__ Wh, const __nv_bfloat16* __restrict__ Wl,
          float* __restrict__ C0, float* __restrict__ C1,
          float* __restrict__ Bm, float* __restrict__ Cm,
          const float* __restrict__ dtb)
{
    extern __shared__ char smem[];
    const uint32_t sb = smem_u32(smem);
    const int tid  = threadIdx.x;
    const int wid  = tid >> 5;
    const int lane = tid & 31;
    const int wy   = wid & 1;
    const int wx   = wid >> 1;
    const int m0 = blockIdx.y * 128, n0 = blockIdx.x * 128;

    float acc[4][4][4];
    #pragma unroll
    for (int i = 0; i < 4; ++i)
        #pragma unroll
        for (int j = 0; j < 4; ++j)
            #pragma unroll
            for (int e = 0; e < 4; ++e) acc[i][j][e] = 0.f;

    const int KT = K >> 5;

    load_stage(sb + 0*STAGE_B, tid, m0, n0,  0, K, Ah, Al, Wh, Wl);
    if (KT > 1) load_stage(sb + 1*STAGE_B, tid, m0, n0, 32, K, Ah, Al, Wh, Wl);

    const int arow = lane & 15;
    const int acol = (lane >> 4) * 16;
    const int brow = (lane & 7) + ((lane >> 4) << 3);
    const int bcol = ((lane >> 3) & 1) * 16;

    for (int kt = 0; kt < KT; ++kt) {
        if (kt + 1 < KT) asm volatile("cp.async.wait_group 1;" ::: "memory");
        else             asm volatile("cp.async.wait_group 0;" ::: "memory");
        __syncthreads();

        const uint32_t st  = sb + (kt & 1) * STAGE_B;
        const uint32_t stb = st + 2 * A_TILE;
        #pragma unroll
        for (int ks = 0; ks < 2; ++ks) {
            uint32_t ah[4][4], al[4][4], bh[4][2], bl[4][2];
            #pragma unroll
            for (int mi = 0; mi < 4; ++mi) {
                uint32_t ra = st + (uint32_t)((wy*64 + mi*16 + arow) * ROWB + ks*32 + acol);
                ldsm4(ah[mi][0], ah[mi][1], ah[mi][2], ah[mi][3], ra);
                ldsm4(al[mi][0], al[mi][1], al[mi][2], al[mi][3], ra + A_TILE);
            }
            #pragma unroll
            for (int p = 0; p < 2; ++p) {
                uint32_t rb = stb + (uint32_t)((wx*32 + p*16 + brow) * ROWB + ks*32 + bcol);
                ldsm4(bh[2*p][0], bh[2*p][1], bh[2*p+1][0], bh[2*p+1][1], rb);
                ldsm4(bl[2*p][0], bl[2*p][1], bl[2*p+1][0], bl[2*p+1][1], rb + B_TILE);
            }
            #pragma unroll
            for (int mi = 0; mi < 4; ++mi)
                #pragma unroll
                for (int ni = 0; ni < 4; ++ni) {
                    mma16816(acc[mi][ni], ah[mi], bh[ni]);
                    mma16816(acc[mi][ni], ah[mi], bl[ni]);
                    mma16816(acc[mi][ni], al[mi], bh[ni]);
                }
        }
        __syncthreads();
        if (kt + 2 < KT)
            load_stage(st, tid, m0, n0, (kt + 2) * 32, K, Ah, Al, Wh, Wl);
    }

    const int r0 = lane >> 2;
    const int c0 = (lane & 3) * 2;
    #pragma unroll
    for (int mi = 0; mi < 4; ++mi)
        #pragma unroll
        for (int ni = 0; ni < 4; ++ni) {
            const int row = m0 + wy*64 + mi*16 + r0;
            const int col = n0 + wx*32 + ni*8 + c0;
            if (EPI == 0) {
                *reinterpret_cast<float2*>(C0 + (size_t)row * N + col) =
                    make_float2(acc[mi][ni][0], acc[mi][ni][1]);
                *reinterpret_cast<float2*>(C0 + (size_t)(row + 8) * N + col) =
                    make_float2(acc[mi][ni][2], acc[mi][ni][3]);
            } else {
                if (col < DINNER) {
                    *reinterpret_cast<float2*>(C0 + (size_t)row * DINNER + col) =
                        make_float2(acc[mi][ni][0], acc[mi][ni][1]);
                    *reinterpret_cast<float2*>(C0 + (size_t)(row + 8) * DINNER + col) =
                        make_float2(acc[mi][ni][2], acc[mi][ni][3]);
                } else if (col < 2*DINNER) {
                    const int dc = col - DINNER;
                    const float b0 = dtb[dc], b1 = dtb[dc + 1];
                    float z0 = acc[mi][ni][0] + b0, z1 = acc[mi][ni][1] + b1;
                    float z2 = acc[mi][ni][2] + b0, z3 = acc[mi][ni][3] + b1;
                    z0 = (z0 > 20.f) ? z0 : log1pf(__expf(z0));
                    z1 = (z1 > 20.f) ? z1 : log1pf(__expf(z1));
                    z2 = (z2 > 20.f) ? z2 : log1pf(__expf(z2));
                    z3 = (z3 > 20.f) ? z3 : log1pf(__expf(z3));
                    *reinterpret_cast<float2*>(C1 + (size_t)row * DINNER + dc) =
                        make_float2(z0, z1);
                    *reinterpret_cast<float2*>(C1 + (size_t)(row + 8) * DINNER + dc) =
                        make_float2(z2, z3);
                } else if (col < 2*DINNER + DSTATE) {
                    const int nn = col - 2*DINNER;
                    *reinterpret_cast<float2*>(Bm + (size_t)row * DSTATE + nn) =
                        make_float2(acc[mi][ni][0], acc[mi][ni][1]);
                    *reinterpret_cast<float2*>(Bm + (size_t)(row + 8) * DSTATE + nn) =
                        make_float2(acc[mi][ni][2], acc[mi][ni][3]);
                } else if (col < 2*DINNER + 2*DSTATE) {
                    const int nn = col - 2*DINNER - DSTATE;
                    *reinterpret_cast<float2*>(Cm + (size_t)row * DSTATE + nn) =
                        make_float2(acc[mi][ni][0], acc[mi][ni][1]);
                    *reinterpret_cast<float2*>(Cm + (size_t)(row + 8) * DSTATE + nn) =
                        make_float2(acc[mi][ni][2], acc[mi][ni][3]);
                }
            }
        }
}

/* ------- depthwise causal conv1d + bias + SiLU -> xc (4 channels/thread) --------- */
#define CTS 64
__global__ void conv_silu(const float* __restrict__ xin,
                          const float* __restrict__ cw,
                          const float* __restrict__ cb,
                          float* __restrict__ xc)
{
    const int d4 = blockIdx.x * blockDim.x + threadIdx.x;
    const int d  = d4 * 4;
    const int b  = blockIdx.z;
    const int t0 = blockIdx.y * CTS;

    float w[4][4], bias[4];
    #pragma unroll
    for (int j = 0; j < 4; ++j) {
        w[j][0] = cw[(d+j)*4+0]; w[j][1] = cw[(d+j)*4+1];
        w[j][2] = cw[(d+j)*4+2]; w[j][3] = cw[(d+j)*4+3];
        bias[j] = cb[d+j];
    }

    const float4* base = reinterpret_cast<const float4*>(
        xin + (size_t)b * SEQLEN * DINNER) + d4;
    const float4 z4 = make_float4(0.f, 0.f, 0.f, 0.f);
    float4 xm3 = (t0 - 3 >= 0) ? base[(size_t)(t0-3) * (DINNER/4)] : z4;
    float4 xm2 = (t0 - 2 >= 0) ? base[(size_t)(t0-2) * (DINNER/4)] : z4;
    float4 xm1 = (t0 - 1 >= 0) ? base[(size_t)(t0-1) * (DINNER/4)] : z4;

    float4* out = reinterpret_cast<float4*>(xc + (size_t)b * SEQLEN * DINNER) + d4;

    #pragma unroll 4
    for (int t = t0; t < t0 + CTS; ++t) {
        float4 cur = base[(size_t)t * (DINNER/4)];
        const float m3[4] = {xm3.x, xm3.y, xm3.z, xm3.w};
        const float m2[4] = {xm2.x, xm2.y, xm2.z, xm2.w};
        const float m1[4] = {xm1.x, xm1.y, xm1.z, xm1.w};
        const float cu[4] = {cur.x, cur.y, cur.z, cur.w};
        float o[4];
        #pragma unroll
        for (int j = 0; j < 4; ++j) {
            float v = fmaf(w[j][0], m3[j], fmaf(w[j][1], m2[j],
                       fmaf(w[j][2], m1[j], fmaf(w[j][3], cu[j], bias[j]))));
            float sig = 1.f / (1.f + __expf(-v));
            o[j] = v * sig;
        }
        out[(size_t)t * (DINNER/4)] = make_float4(o[0], o[1], o[2], o[3]);
        xm3 = xm2; xm2 = xm1; xm1 = cur;
    }
}

/* ------- scan pass 1 (1 ch/thread): Σdt trick + ex2 + float4 Bs loads ------------ */
__global__ __launch_bounds__(128)
void scan_pass1(const float* __restrict__ delta, const float* __restrict__ xc,
                const float* __restrict__ Bm, const float* __restrict__ A_log,
                float* __restrict__ ap_out, float* __restrict__ he_out)
{
    __shared__ float Bs[CHUNK*DSTATE];
    const int tid = threadIdx.x;
    const int d = blockIdx.x * 128 + tid;
    const int c = blockIdx.y, b = blockIdx.z;

    const float* Bsrc = Bm + ((size_t)b * SEQLEN + (size_t)c * CHUNK) * DSTATE;
    for (int i = tid; i < CHUNK*DSTATE; i += 128) Bs[i] = Bsrc[i];
    __syncthreads();
    const float4* Bs4 = reinterpret_cast<const float4*>(Bs);

    float A2[DSTATE];
    #pragma unroll
    for (int s = 0; s < DSTATE; ++s)
        A2[s] = -expf(A_log[d*DSTATE + s]) * LOG2E;

    float h[DSTATE];
    #pragma unroll
    for (int s = 0; s < DSTATE; ++s) h[s] = 0.f;
    float sdt = 0.f;

    const size_t rowbase = ((size_t)b * SEQLEN + (size_t)c * CHUNK) * DINNER + d;
    const float* dptr = delta + rowbase;
    const float* xptr = xc + rowbase;

    for (int tl = 0; tl < CHUNK; ++tl) {
        float dt = dptr[(size_t)tl * DINNER];
        float xv = xptr[(size_t)tl * DINNER];
        float dx = dt * xv;
        sdt += dt;
        #pragma unroll
        for (int q = 0; q < 4; ++q) {
            float4 bq = Bs4[tl*4 + q];
            const float bv[4] = {bq.x, bq.y, bq.z, bq.w};
            #pragma unroll
            for (int e = 0; e < 4; ++e) {
                const int s = q*4 + e;
                float a = ex2f(dt * A2[s]);
                h[s] = fmaf(a, h[s], dx * bv[e]);
            }
        }
    }

    const size_t o = (((size_t)b * DINNER + d) * NCH + c) * DSTATE;
    #pragma unroll
    for (int s = 0; s < DSTATE; ++s) {
        ap_out[o+s] = ex2f(sdt * A2[s]);
        he_out[o+s] = h[s];
    }
}

/* ------- scan pass 2: sequential stitch over chunks; he buffer -> chunk inits ---- */
__global__ void scan_pass2(const float* __restrict__ ap, float* __restrict__ he)
{
    const int idx = blockIdx.x * blockDim.x + threadIdx.x;
    if (idx >= BATCH*DINNER) return;
    float h[DSTATE];
    #pragma unroll
    for (int s = 0; s < DSTATE; ++s) h[s] = 0.f;
    for (int c = 0; c < NCH; ++c) {
        const size_t o = ((size_t)idx * NCH + c) * DSTATE;
        #pragma unroll
        for (int s = 0; s < DSTATE; ++s) {
            float hin = h[s];
            h[s] = fmaf(ap[o+s], hin, he[o+s]);
            he[o+s] = hin;
        }
    }
}

/* --- scan pass 3 (2 ch/thread): ex2 + float4 Bs/Cs loads, bf162 stores ----------- */
__global__ __launch_bounds__(128)
void scan_pass3(const float* __restrict__ delta, const float* __restrict__ xc,
                const float* __restrict__ Bm, const float* __restrict__ Cm,
                const float* __restrict__ A_log, const float* __restrict__ Dv,
                const float* __restrict__ hinit,
                __nv_bfloat16* __restrict__ yhi, __nv_bfloat16* __restrict__ ylo)
{
    __shared__ float Bs[CHUNK*DSTATE];
    __shared__ float Cs[CHUNK*DSTATE];
    const int tid = threadIdx.x;
    const int d0 = (blockIdx.x * 128 + tid) * 2;
    const int c = blockIdx.y, b = blockIdx.z;

    const float* Bsrc = Bm + ((size_t)b * SEQLEN + (size_t)c * CHUNK) * DSTATE;
    const float* Csrc = Cm + ((size_t)b * SEQLEN + (size_t)c * CHUNK) * DSTATE;
    for (int i = tid; i < CHUNK*DSTATE; i += 128) { Bs[i] = Bsrc[i]; Cs[i] = Csrc[i]; }
    __syncthreads();
    const float4* Bs4 = reinterpret_cast<const float4*>(Bs);
    const float4* Cs4 = reinterpret_cast<const float4*>(Cs);

    float A20[DSTATE], A21[DSTATE];
    #pragma unroll
    for (int s = 0; s < DSTATE; ++s) {
        A20[s] = -expf(A_log[d0*DSTATE + s]) * LOG2E;
        A21[s] = -expf(A_log[(d0+1)*DSTATE + s]) * LOG2E;
    }

    float h0[DSTATE], h1[DSTATE];
    const size_t o0 = (((size_t)b * DINNER + d0) * NCH + c) * DSTATE;
    const size_t o1 = o0 + (size_t)NCH * DSTATE;
    #pragma unroll
    for (int s = 0; s < DSTATE; ++s) { h0[s] = hinit[o0+s]; h1[s] = hinit[o1+s]; }

    const float Dd0 = Dv[d0], Dd1 = Dv[d0+1];
    const size_t rowbase = ((size_t)b * SEQLEN + (size_t)c * CHUNK) * DINNER + d0;
    const float2* dptr = reinterpret_cast<const float2*>(delta + rowbase);
    const float2* xptr = reinterpret_cast<const float2*>(xc + rowbase);
    __nv_bfloat162* yhp = reinterpret_cast<__nv_bfloat162*>(yhi + rowbase);
    __nv_bfloat162* ylp = reinterpret_cast<__nv_bfloat162*>(ylo + rowbase);

    for (int tl = 0; tl < CHUNK; ++tl) {
        float2 dt = dptr[(size_t)tl * (DINNER/2)];
        float2 xv = xptr[(size_t)tl * (DINNER/2)];
        float dx0 = dt.x * xv.x, dx1 = dt.y * xv.y;
        float acc0 = 0.f, acc1 = 0.f;
        #pragma unroll
        for (int q = 0; q < 4; ++q) {
            float4 bq = Bs4[tl*4 + q];
            float4 cq = Cs4[tl*4 + q];
            const float bv[4] = {bq.x, bq.y, bq.z, bq.w};
            const float cv[4] = {cq.x, cq.y, cq.z, cq.w};
            #pragma unroll
            for (int e = 0; e < 4; ++e) {
                const int s = q*4 + e;
                float a0 = ex2f(dt.x * A20[s]);
                float a1 = ex2f(dt.y * A21[s]);
                h0[s] = fmaf(a0, h0[s], dx0 * bv[e]);
                h1[s] = fmaf(a1, h1[s], dx1 * bv[e]);
                acc0 = fmaf(h0[s], cv[e], acc0);
                acc1 = fmaf(h1[s], cv[e], acc1);
            }
        }
        float y0 = fmaf(Dd0, xv.x, acc0);
        float y1 = fmaf(Dd1, xv.y, acc1);
        __nv_bfloat16 hb0 = __float2bfloat16(y0);
        __nv_bfloat16 hb1 = __float2bfloat16(y1);
        __nv_bfloat16 lb0 = __float2bfloat16(y0 - __bfloat162float(hb0));
        __nv_bfloat16 lb1 = __float2bfloat16(y1 - __bfloat162float(hb1));
        yhp[(size_t)tl * (DINNER/2)] = __halves2bfloat162(hb0, hb1);
        ylp[(size_t)tl * (DINNER/2)] = __halves2bfloat162(lb0, lb1);
    }
}

/* -------------------------------- launcher --------------------------------------- */
extern "C" void kernel_launch(void* const* d_in, const int* in_sizes, int n_in,
                              void* d_out, int out_size)
{
    const float* x         = (const float*)d_in[0];
    const float* x_proj_w  = (const float*)d_in[1];
    const float* dt_proj_w = (const float*)d_in[2];
    const float* dt_proj_b = (const float*)d_in[3];
    const float* A_log     = (const float*)d_in[4];
    const float* Dvec      = (const float*)d_in[5];
    const float* B_proj_w  = (const float*)d_in[6];
    const float* C_proj_w  = (const float*)d_in[7];
    const float* conv_w    = (const float*)d_in[8];
    const float* conv_b    = (const float*)d_in[9];
    const float* out_proj_w= (const float*)d_in[10];
    float* out = (float*)d_out;

    float *xinner, *xc, *delta, *Bm, *Cm, *ap, *he;
    __nv_bfloat16 *xhi, *xlo, *whi, *wlo, *w2hi, *w2lo, *yhi, *ylo;
    cudaGetSymbolAddress((void**)&xinner, g_xinner);
    cudaGetSymbolAddress((void**)&xc,     g_xc);
    cudaGetSymbolAddress((void**)&delta,  g_delta);
    cudaGetSymbolAddress((void**)&Bm,     g_Bm);
    cudaGetSymbolAddress((void**)&Cm,     g_Cm);
    cudaGetSymbolAddress((void**)&ap,     g_ap);
    cudaGetSymbolAddress((void**)&he,     g_he);
    cudaGetSymbolAddress((void**)&xhi,    g_xhi);
    cudaGetSymbolAddress((void**)&xlo,    g_xlo);
    cudaGetSymbolAddress((void**)&whi,    g_whi);
    cudaGetSymbolAddress((void**)&wlo,    g_wlo);
    cudaGetSymbolAddress((void**)&w2hi,   g_w2hi);
    cudaGetSymbolAddress((void**)&w2lo,   g_w2lo);
    cudaGetSymbolAddress((void**)&yhi,    g_yhi);
    cudaGetSymbolAddress((void**)&ylo,    g_ylo);

    cudaFuncSetAttribute(hmma_gemm<0>, cudaFuncAttributeMaxDynamicSharedMemorySize, SMEM_GEMM);
    cudaFuncSetAttribute(hmma_gemm<1>, cudaFuncAttributeMaxDynamicSharedMemorySize, SMEM_GEMM);

    /* 1: split x + all GEMM1 weights */
    split_pre<<<PRE_TOT/256, 256>>>(x, x_proj_w, dt_proj_w, B_proj_w, C_proj_w,
                                    xhi, xlo, whi, wlo);

    /* 2: fused GEMM -> xinner, delta(softplus), Bm, Cm */
    hmma_gemm<1><<<dim3(NFUSED/128, NTOK/128), 256, SMEM_GEMM>>>(
        NTOK, NFUSED, DMODEL, xhi, xlo, whi, wlo, xinner, delta, Bm, Cm, dt_proj_b);

    /* 3: conv + SiLU -> xc */
    conv_silu<<<dim3(DINNER/4/256, SEQLEN/CTS, BATCH), 256>>>(xinner, conv_w, conv_b, xc);

    /* 4: scan pass 1 (1 ch/thread) */
    scan_pass1<<<dim3(DINNER/128, NCH, BATCH), 128>>>(delta, xc, Bm, A_log, ap, he);

    scan_pass2<<<(BATCH*DINNER + 127)/128, 128>>>(ap, he);

    /* scan pass 3 (2 ch/thread, bf162 stores) */
    scan_pass3<<<dim3(DINNER/256, NCH, BATCH), 128>>>(delta, xc, Bm, Cm, A_log, Dvec,
                                                      he, yhi, ylo);

    split_bf16<<<DMODEL*DINNER/4/256, 256>>>(out_proj_w, w2hi, w2lo, DMODEL*DINNER/4);

    /* out = y @ out_proj_w^T */
    hmma_gemm<0><<<dim3(DMODEL/128, NTOK/128), 256, SMEM_GEMM>>>(
        NTOK, DMODEL, DINNER, yhi, ylo, w2hi, w2lo, out, nullptr, nullptr, nullptr, nullptr);
}